// round 11
// baseline (speedup 1.0000x reference)
#include <cuda_runtime.h>

#define IW 1920
#define IH 1080
#define IB 8
#define NPIX (IW * IH)
#define NTOT (IB * NPIX)
#define WPR  (IW / 32)            // 60 packed words per row
#define NWORDS (NTOT / 32)        // 518400
#define BORDER_WORDS_PER_IMG (60 + 60 + 1078 * 2)   // 2276

#define TH 24                     // output tile height (1080/24 = 45)

// Scratch (no cudaMalloc allowed)
__device__ unsigned char g_dir[NTOT];
__device__ unsigned int  g_pe0[NWORDS], g_pl0[NWORDS];   // after NMS/threshold
__device__ unsigned int  g_pe1[NWORDS], g_pl1[NWORDS];   // after hysteresis iter 1

// Sobel with immediate weights (zero-weight terms skipped; original fmaf order).
__device__ __forceinline__ void sobel_win(float v00, float v01, float v02,
                                          float v10, float v12,
                                          float v20, float v21, float v22,
                                          float& gxv, float& gyv) {
    float gx = 0.f;
    gx = fmaf(-0.125f, v00, gx);
    gx = fmaf( 0.125f, v02, gx);
    gx = fmaf(-0.25f,  v10, gx);
    gx = fmaf( 0.25f,  v12, gx);
    gx = fmaf(-0.125f, v20, gx);
    gx = fmaf( 0.125f, v22, gx);
    float gy = 0.f;
    gy = fmaf(-0.125f, v00, gy);
    gy = fmaf(-0.25f,  v01, gy);
    gy = fmaf(-0.125f, v02, gy);
    gy = fmaf( 0.125f, v20, gy);
    gy = fmaf( 0.25f,  v21, gy);
    gy = fmaf( 0.125f, v22, gy);
    gxv = gx; gyv = gy;
}

// Window top-left = (r, c): reads gsm[r..r+2][c..c+2].
__device__ __forceinline__ void sobel_px(const float (*gsm)[40], int r, int c,
                                         float& gxv, float& gyv) {
    sobel_win(gsm[r+0][c+0], gsm[r+0][c+1], gsm[r+0][c+2],
              gsm[r+1][c+0],                gsm[r+1][c+2],
              gsm[r+2][c+0], gsm[r+2][c+1], gsm[r+2][c+2], gxv, gyv);
}

// ang/deg/cls chain — bit-identical to previous rounds.
__device__ __forceinline__ void ang_chain(float gx_, float gy_, float& am, int& cls) {
    float ang = atan2f(gy_, gx_);
    float t = ang + 3.14159274101257324f;            // float32(pi)
    if (t >= 6.28318548202514648f) t -= 6.28318548202514648f;   // == fmodf(t, 2pi)
    float deg = t * 57.2957801818847656f;            // float32(180/pi)
    am = deg;
    if (am >= 180.0f) am -= 180.0f;                  // == fmodf(deg, 180)
    if (am >= 180.0f) am -= 180.0f;
    int q = (int)rintf(deg / 45.0f);                 // round-half-even == jnp.round
    cls = q & 3;
}

// ---------------------------------------------------------------------------
// Kernel 1: fused gaussian(5x5) + sobel + mag*255 + ang + NMS + threshold.
// Interior fast path; vectorized tile load; 4-col-blocked sobel with STG.128;
// halo-ring sobel on otherwise-idle warps 6-7; slim NMS stage.
// Border words (jnp.roll wrap) recomputed by k_border afterwards.
// ---------------------------------------------------------------------------
__global__ void k_fused(const float* __restrict__ x,
                        float* __restrict__ magOut, float* __restrict__ angOut) {
    // gaussian = [[2,4,5,4,2],[4,9,12,9,4],[5,12,15,12,5],[4,9,12,9,4],[2,4,5,4,2]]/159
    constexpr float GW[25] = {
        2.0f/159.0f, 4.0f/159.0f,  5.0f/159.0f, 4.0f/159.0f, 2.0f/159.0f,
        4.0f/159.0f, 9.0f/159.0f, 12.0f/159.0f, 9.0f/159.0f, 4.0f/159.0f,
        5.0f/159.0f,12.0f/159.0f, 15.0f/159.0f,12.0f/159.0f, 5.0f/159.0f,
        4.0f/159.0f, 9.0f/159.0f, 12.0f/159.0f, 9.0f/159.0f, 4.0f/159.0f,
        2.0f/159.0f, 4.0f/159.0f,  5.0f/159.0f, 4.0f/159.0f, 2.0f/159.0f };
    __shared__ float sin_[32][40];     // raw input, rows by-4..by+27, cols bx-4..bx+35
    __shared__ float gsm[28][40];      // smoothed/255, row r <-> Y=by+r-2, col c <-> X=bx+c-2 (36 used)
    __shared__ float magS[26][40];     // mag*255, row r <-> Y=by+r-1, col c <-> X=bx+c-4 (c 3..36 used)
    __shared__ unsigned int dirS[24][8]; // packed cls, 4 px per word
    const int b  = blockIdx.z;
    const int bx = blockIdx.x * 32, by = blockIdx.y * TH;
    const int tx = threadIdx.x, ty = threadIdx.y;
    const int tid = ty * 32 + tx;
    const float* img = x + b * NPIX;
    const bool interior = (blockIdx.x > 0) & (blockIdx.x < 59) &
                          (blockIdx.y > 0) & (blockIdx.y < 44);
    // ---- stage 0: raw input tile ----
    if (interior) {
        // 32 rows x 10 float4 = 320 vector loads
#pragma unroll
        for (int it = 0; it < 2; it++) {
            const int i = tid + it * 256;
            if (i < 320) {
                const int r = i / 10, c4 = i - r * 10;
                const int yy = by + r - 4;
                *(float4*)&sin_[r][4 * c4] =
                    *(const float4*)&img[yy * IW + bx + 4 * c4 - 4];
            }
        }
    } else {
#pragma unroll
        for (int k = 0; k < 4; k++) {
            const int r = ty + 8 * k;
            const int yy = by + r - 4;
            {
                const int xx = bx + tx - 4;
                float v = 0.f;
                if (yy >= 0 && yy < IH && xx >= 0 && xx < IW) v = img[yy * IW + xx];
                sin_[r][tx] = v;
            }
            if (tx < 8) {
                const int xx = bx + tx + 28;
                float v = 0.f;
                if (yy >= 0 && yy < IH && xx >= 0 && xx < IW) v = img[yy * IW + xx];
                sin_[r][tx + 32] = v;
            }
        }
    }
    __syncthreads();
    // ---- stage 1: gaussian, 4 outputs per thread (28 rows x 9 groups = 252) ----
    if (tid < 252) {
        const int r = tid / 9;
        const int c0 = (tid - r * 9) * 4;
        float W[5][8];
#pragma unroll
        for (int di = 0; di < 5; di++) {
            const float4 lo = *(const float4*)&sin_[r + di][c0];
            const float4 hi = *(const float4*)&sin_[r + di][c0 + 4];
            W[di][0] = lo.x; W[di][1] = lo.y; W[di][2] = lo.z; W[di][3] = lo.w;
            W[di][4] = hi.x; W[di][5] = hi.y; W[di][6] = hi.z; W[di][7] = hi.w;
        }
        float s0 = 0.f, s1 = 0.f, s2 = 0.f, s3 = 0.f;
#pragma unroll
        for (int di = 0; di < 5; di++)
#pragma unroll
            for (int dj = 0; dj < 5; dj++) {
                const float wgt = GW[di * 5 + dj];
                s0 = fmaf(wgt, W[di][dj + 0], s0);
                s1 = fmaf(wgt, W[di][dj + 1], s1);
                s2 = fmaf(wgt, W[di][dj + 2], s2);
                s3 = fmaf(wgt, W[di][dj + 3], s3);
            }
        float4 o;
        if (interior) {
            o.x = s0 * (1.0f / 255.0f);
            o.y = s1 * (1.0f / 255.0f);
            o.z = s2 * (1.0f / 255.0f);
            o.w = s3 * (1.0f / 255.0f);
        } else {
            const int yy = by + r - 2;
            const bool rowOk = (yy >= 0 && yy < IH);
            const int xx0 = bx + c0 - 2;
            o.x = (rowOk && xx0 + 0 >= 0 && xx0 + 0 < IW) ? s0 * (1.0f / 255.0f) : 0.f;
            o.y = (rowOk && xx0 + 1 >= 0 && xx0 + 1 < IW) ? s1 * (1.0f / 255.0f) : 0.f;
            o.z = (rowOk && xx0 + 2 >= 0 && xx0 + 2 < IW) ? s2 * (1.0f / 255.0f) : 0.f;
            o.w = (rowOk && xx0 + 3 >= 0 && xx0 + 3 < IW) ? s3 * (1.0f / 255.0f) : 0.f;
        }
        *(float4*)&gsm[r][c0] = o;
    }
    __syncthreads();
    // ---- stage 2a: interior 4-col groups (24 rows x 8 groups = 192 threads) ----
    // magS row r <-> image Y = by + r - 1; window rows = r, r+1, r+2.
    const bool colBorder = (blockIdx.x == 0) | (blockIdx.x == WPR - 1);
    if (tid < 192) {
        const int r = (tid >> 3) + 1;          // 1..24
        const int k = tid & 7;                 // 0..7
        float w0[8], w1[8], w2[8];
        {
            const float4 a0 = *(const float4*)&gsm[r][4 * k];
            const float4 a1 = *(const float4*)&gsm[r][4 * k + 4];
            w0[0]=a0.x; w0[1]=a0.y; w0[2]=a0.z; w0[3]=a0.w;
            w0[4]=a1.x; w0[5]=a1.y; w0[6]=a1.z; w0[7]=a1.w;
            const float4 b0 = *(const float4*)&gsm[r + 1][4 * k];
            const float4 b1 = *(const float4*)&gsm[r + 1][4 * k + 4];
            w1[0]=b0.x; w1[1]=b0.y; w1[2]=b0.z; w1[3]=b0.w;
            w1[4]=b1.x; w1[5]=b1.y; w1[6]=b1.z; w1[7]=b1.w;
            const float4 c0_ = *(const float4*)&gsm[r + 2][4 * k];
            const float4 c1_ = *(const float4*)&gsm[r + 2][4 * k + 4];
            w2[0]=c0_.x; w2[1]=c0_.y; w2[2]=c0_.z; w2[3]=c0_.w;
            w2[4]=c1_.x; w2[5]=c1_.y; w2[6]=c1_.z; w2[7]=c1_.w;
        }
        float mg[4], an[4];
        unsigned int clsPack = 0;
#pragma unroll
        for (int j = 0; j < 4; j++) {
            float gx_, gy_;
            sobel_win(w0[j+1], w0[j+2], w0[j+3],
                      w1[j+1],          w1[j+3],
                      w2[j+1], w2[j+2], w2[j+3], gx_, gy_);
            mg[j] = sqrtf(gx_ * gx_ + gy_ * gy_ + 1e-6f) * 255.0f;
            float am; int cls;
            ang_chain(gx_, gy_, am, cls);
            an[j] = am;
            clsPack |= (unsigned)cls << (8 * j);
        }
        *(float4*)&magS[r][4 * k + 4] = make_float4(mg[0], mg[1], mg[2], mg[3]);
        dirS[r - 1][k] = clsPack;
        const int Y = by + r - 1;
        const int idx = b * NPIX + Y * IW + bx + 4 * k;
        *(float4*)&magOut[idx] = make_float4(mg[0], mg[1], mg[2], mg[3]);
        *(float4*)&angOut[idx] = make_float4(an[0], an[1], an[2], an[3]);
        if (Y == 0 || Y == IH - 1 || colBorder) {
            uchar4 d4;
            d4.x = (unsigned char)(clsPack & 3);
            d4.y = (unsigned char)((clsPack >> 8) & 3);
            d4.z = (unsigned char)((clsPack >> 16) & 3);
            d4.w = (unsigned char)((clsPack >> 24) & 3);
            *(uchar4*)&g_dir[idx] = d4;
        }
    } else {
        // ---- stage 2b on warps 6-7 (64 threads, 116 halo-ring items) ----
#pragma unroll
        for (int it = 0; it < 2; it++) {
            const int u = (tid - 192) + it * 64;
            if (u < 116) {
                int r, c;
                if (u < 34)      { r = 0;         c = 3 + u; }
                else if (u < 68) { r = 25;        c = 3 + (u - 34); }
                else if (u < 92) { r = u - 67;    c = 3; }          // rows 1..24
                else             { r = u - 91;    c = 36; }         // rows 1..24
                float gxv, gyv;
                sobel_px(gsm, r, c - 3, gxv, gyv);  // window rows r..r+2, cols c-3..c-1
                magS[r][c] = sqrtf(gxv * gxv + gyv * gyv + 1e-6f) * 255.0f;
            }
        }
    }
    __syncthreads();
    // ---- stage 3: NMS only (3 rows per thread) ----
#pragma unroll
    for (int s = 0; s < 3; s++) {
        const int o = ty + 8 * s;            // output row within tile (warp-uniform)
        const int Y = by + o;
        const int r0 = o + 1, c0 = tx + 4;   // magS coords of own pixel
        const float m255 = magS[r0][c0];
        const int cls = (int)((dirS[o][tx >> 2] >> (8 * (tx & 3))) & 3u);
        // cls0: (y,xr)/(y,xl)  cls1: (yd,xr)/(yu,x) [ref bug kept]
        // cls2: (yd,x)/(yu,x)  cls3: (yd,xl)/(yu,xr)
        int ar = (cls == 0) ? r0 : r0 + 1;
        int ac = (cls == 2) ? c0 : ((cls == 3) ? c0 - 1 : c0 + 1);
        int cr = (cls == 0) ? r0 : r0 - 1;
        int cc = (cls == 0) ? c0 - 1 : ((cls == 3) ? c0 + 1 : c0);
        float a = magS[ar][ac];
        float c = magS[cr][cc];
        float sup = (m255 > a && m255 > c) ? m255 : 0.f;
        unsigned we = __ballot_sync(0xffffffffu, sup > 150.0f);
        unsigned wl = __ballot_sync(0xffffffffu, sup >= 50.0f && sup < 150.0f);
        if (tx == 0) {
            const int widx = (b * IH + Y) * WPR + blockIdx.x;
            g_pe0[widx] = we;
            g_pl0[widx] = wl;
        }
    }
}

// ---------------------------------------------------------------------------
// Kernel 2: recompute NMS/threshold for border words (rows 0 & 1079, word
// cols 0 & 59) with jnp.roll wrap-around. One warp per word.
// ---------------------------------------------------------------------------
__global__ void k_border(const float* __restrict__ mag) {
    const int W = blockIdx.x * 8 + threadIdx.y;          // warp id
    const int lane = threadIdx.x;
    const int b = W / BORDER_WORDS_PER_IMG;
    const int u = W % BORDER_WORDS_PER_IMG;
    int y, w;
    if (u < 60)       { y = 0;        w = u; }
    else if (u < 120) { y = IH - 1;   w = u - 60; }
    else { int v = u - 120; y = 1 + (v >> 1); w = (v & 1) ? (WPR - 1) : 0; }
    const int x = w * 32 + lane;
    const float* p = mag + b * NPIX;
    const int idx = b * NPIX + y * IW + x;
    const float m0 = p[y * IW + x];
    const int xl = (x == 0) ? (IW - 1) : (x - 1);
    const int xr = (x == IW - 1) ? 0 : (x + 1);
    const int yu = (y == 0) ? (IH - 1) : (y - 1);
    const int yd = (y == IH - 1) ? 0 : (y + 1);
    const int cls = g_dir[idx];
    int ay = (cls == 0) ? y : yd;
    int ax = (cls == 2) ? x : ((cls == 3) ? xl : xr);
    int cy = (cls == 0) ? y : yu;
    int cx = (cls == 0) ? xl : ((cls == 3) ? xr : x);
    float a = p[ay * IW + ax];
    float c = p[cy * IW + cx];
    float sup = (m0 > a && m0 > c) ? m0 : 0.f;
    unsigned we = __ballot_sync(0xffffffffu, sup > 150.0f);
    unsigned wl = __ballot_sync(0xffffffffu, sup >= 50.0f && sup < 150.0f);
    if (lane == 0) {
        const int widx = (b * IH + y) * WPR + w;
        g_pe0[widx] = we;
        g_pl0[widx] = wl;
    }
}

// ---------------------------------------------------------------------------
// Bit helper: OR of {left,center,right} horizontal neighbors of a word row.
// ---------------------------------------------------------------------------
__device__ __forceinline__ unsigned hor3(unsigned L, unsigned M, unsigned R) {
    return M | (M << 1) | (M >> 1) | (L >> 31) | (R << 31);
}

// ---------------------------------------------------------------------------
// Kernel 3: hysteresis iteration 1, fully bit-packed, word per thread.
// ---------------------------------------------------------------------------
__global__ void k_hyst1() {
    const int t = blockIdx.x * 256 + threadIdx.x;
    const int w = t % WPR;
    const int rem = t / WPR;
    const int y = rem % IH;
    const int base = t - w;
    unsigned nbr = 0, e = 0;
#pragma unroll
    for (int dy = -1; dy <= 1; dy++) {
        const int yy = y + dy;
        if (yy < 0 || yy >= IH) continue;
        const int rb = base + dy * WPR;
        unsigned L = (w > 0)       ? g_pe0[rb + w - 1] : 0u;
        unsigned M =                 g_pe0[rb + w];
        unsigned R = (w < WPR - 1) ? g_pe0[rb + w + 1] : 0u;
        nbr |= hor3(L, M, R);
        if (dy == 0) e = M;
    }
    const unsigned l = g_pl0[t];
    const unsigned conn = nbr & l;
    g_pe1[t] = e | conn;
    g_pl1[t] = l & ~conn;
}

// ---------------------------------------------------------------------------
// Kernel 4: hysteresis iteration 2 + final edges*255 float store.
// Word per thread; thread owns one 128B output cacheline -> 8x STG.128.
// ---------------------------------------------------------------------------
__global__ void k_hyst2(float* __restrict__ outE) {
    const int t = blockIdx.x * 256 + threadIdx.x;
    const int w = t % WPR;
    const int rem = t / WPR;
    const int y = rem % IH;
    const int base = t - w;
    unsigned nbr = 0, e = 0;
#pragma unroll
    for (int dy = -1; dy <= 1; dy++) {
        const int yy = y + dy;
        if (yy < 0 || yy >= IH) continue;
        const int rb = base + dy * WPR;
        unsigned L = (w > 0)       ? g_pe1[rb + w - 1] : 0u;
        unsigned M =                 g_pe1[rb + w];
        unsigned R = (w < WPR - 1) ? g_pe1[rb + w + 1] : 0u;
        nbr |= hor3(L, M, R);
        if (dy == 0) e = M;
    }
    const unsigned l = g_pl1[t];
    const unsigned enew = e | (nbr & l);
    float* dst = outE + t * 32;
#pragma unroll
    for (int jj = 0; jj < 8; jj++) {
        float4 v;
        v.x = ((enew >> (4 * jj + 0)) & 1u) ? 255.0f : 0.0f;
        v.y = ((enew >> (4 * jj + 1)) & 1u) ? 255.0f : 0.0f;
        v.z = ((enew >> (4 * jj + 2)) & 1u) ? 255.0f : 0.0f;
        v.w = ((enew >> (4 * jj + 3)) & 1u) ? 255.0f : 0.0f;
        *(float4*)&dst[4 * jj] = v;
    }
}

extern "C" void kernel_launch(void* const* d_in, const int* in_sizes, int n_in,
                              void* d_out, int out_size) {
    const float* x = (const float*)d_in[0];
    float* out       = (float*)d_out;
    float* out_edges = out;
    float* out_mag   = out + NTOT;
    float* out_ang   = out + 2 * NTOT;

    dim3 blk(32, 8, 1);
    dim3 grd(IW / 32, IH / TH, IB);

    k_fused<<<grd, blk>>>(x, out_mag, out_ang);
    k_border<<<(IB * BORDER_WORDS_PER_IMG) / 8, blk>>>(out_mag);
    k_hyst1<<<NWORDS / 256, 256>>>();
    k_hyst2<<<NWORDS / 256, 256>>>(out_edges);
}

// round 12
// speedup vs baseline: 1.0690x; 1.0690x over previous
#include <cuda_runtime.h>

#define IW 1920
#define IH 1080
#define IB 8
#define NPIX (IW * IH)
#define NTOT (IB * NPIX)
#define WPR  (IW / 32)            // 60 packed words per row
#define NWORDS (NTOT / 32)        // 518400
#define BORDER_WORDS_PER_IMG (60 + 60 + 1078 * 2)   // 2276

#define TH 24                     // output tile height (1080/24 = 45)

// Scratch (no cudaMalloc allowed)
__device__ unsigned char g_dir[NTOT];
__device__ unsigned int  g_pe0[NWORDS], g_pl0[NWORDS];   // after NMS/threshold
__device__ unsigned int  g_pe1[NWORDS], g_pl1[NWORDS];   // after hysteresis iter 1

// Sobel with immediate weights (zero-weight terms skipped; original fmaf order).
__device__ __forceinline__ void sobel_win(float v00, float v01, float v02,
                                          float v10, float v12,
                                          float v20, float v21, float v22,
                                          float& gxv, float& gyv) {
    float gx = 0.f;
    gx = fmaf(-0.125f, v00, gx);
    gx = fmaf( 0.125f, v02, gx);
    gx = fmaf(-0.25f,  v10, gx);
    gx = fmaf( 0.25f,  v12, gx);
    gx = fmaf(-0.125f, v20, gx);
    gx = fmaf( 0.125f, v22, gx);
    float gy = 0.f;
    gy = fmaf(-0.125f, v00, gy);
    gy = fmaf(-0.25f,  v01, gy);
    gy = fmaf(-0.125f, v02, gy);
    gy = fmaf( 0.125f, v20, gy);
    gy = fmaf( 0.25f,  v21, gy);
    gy = fmaf( 0.125f, v22, gy);
    gxv = gx; gyv = gy;
}

// Window top-left = (r, c): reads gsm[r..r+2][c..c+2].
__device__ __forceinline__ void sobel_px(const float (*gsm)[40], int r, int c,
                                         float& gxv, float& gyv) {
    sobel_win(gsm[r+0][c+0], gsm[r+0][c+1], gsm[r+0][c+2],
              gsm[r+1][c+0],                gsm[r+1][c+2],
              gsm[r+2][c+0], gsm[r+2][c+1], gsm[r+2][c+2], gxv, gyv);
}

// ang/deg/cls chain — bit-identical to previous rounds.
__device__ __forceinline__ void ang_chain(float gx_, float gy_, float& am, int& cls) {
    float ang = atan2f(gy_, gx_);
    float t = ang + 3.14159274101257324f;            // float32(pi)
    if (t >= 6.28318548202514648f) t -= 6.28318548202514648f;   // == fmodf(t, 2pi)
    float deg = t * 57.2957801818847656f;            // float32(180/pi)
    am = deg;
    if (am >= 180.0f) am -= 180.0f;                  // == fmodf(deg, 180)
    if (am >= 180.0f) am -= 180.0f;
    int q = (int)rintf(deg / 45.0f);                 // round-half-even == jnp.round
    cls = q & 3;
}

// ---------------------------------------------------------------------------
// Kernel 1: fused gaussian(5x5) + sobel + mag*255 + ang + NMS + threshold.
// Interior fast path; vectorized tile load; 4-col-blocked sobel with STG.128;
// halo-ring sobel on otherwise-idle warps 6-7; slim NMS stage.
// Border words (jnp.roll wrap) recomputed by k_border afterwards.
// ---------------------------------------------------------------------------
__global__ void k_fused(const float* __restrict__ x,
                        float* __restrict__ magOut, float* __restrict__ angOut) {
    // gaussian = [[2,4,5,4,2],[4,9,12,9,4],[5,12,15,12,5],[4,9,12,9,4],[2,4,5,4,2]]/159
    constexpr float GW[25] = {
        2.0f/159.0f, 4.0f/159.0f,  5.0f/159.0f, 4.0f/159.0f, 2.0f/159.0f,
        4.0f/159.0f, 9.0f/159.0f, 12.0f/159.0f, 9.0f/159.0f, 4.0f/159.0f,
        5.0f/159.0f,12.0f/159.0f, 15.0f/159.0f,12.0f/159.0f, 5.0f/159.0f,
        4.0f/159.0f, 9.0f/159.0f, 12.0f/159.0f, 9.0f/159.0f, 4.0f/159.0f,
        2.0f/159.0f, 4.0f/159.0f,  5.0f/159.0f, 4.0f/159.0f, 2.0f/159.0f };
    __shared__ float sin_[32][40];     // raw input, rows by-4..by+27, cols bx-4..bx+35
    __shared__ float gsm[28][40];      // smoothed/255, row r <-> Y=by+r-2, col c <-> X=bx+c-2 (36 used)
    __shared__ float magS[26][40];     // mag*255, row r <-> Y=by+r-1, col c <-> X=bx+c-4 (c 3..36 used)
    __shared__ unsigned int dirS[24][8]; // packed cls, 4 px per word
    const int b  = blockIdx.z;
    const int bx = blockIdx.x * 32, by = blockIdx.y * TH;
    const int tx = threadIdx.x, ty = threadIdx.y;
    const int tid = ty * 32 + tx;
    const float* img = x + b * NPIX;
    const bool interior = (blockIdx.x > 0) & (blockIdx.x < 59) &
                          (blockIdx.y > 0) & (blockIdx.y < 44);
    // ---- stage 0: raw input tile ----
    if (interior) {
        // 32 rows x 10 float4 = 320 vector loads
#pragma unroll
        for (int it = 0; it < 2; it++) {
            const int i = tid + it * 256;
            if (i < 320) {
                const int r = i / 10, c4 = i - r * 10;
                const int yy = by + r - 4;
                *(float4*)&sin_[r][4 * c4] =
                    *(const float4*)&img[yy * IW + bx + 4 * c4 - 4];
            }
        }
    } else {
#pragma unroll
        for (int k = 0; k < 4; k++) {
            const int r = ty + 8 * k;
            const int yy = by + r - 4;
            {
                const int xx = bx + tx - 4;
                float v = 0.f;
                if (yy >= 0 && yy < IH && xx >= 0 && xx < IW) v = img[yy * IW + xx];
                sin_[r][tx] = v;
            }
            if (tx < 8) {
                const int xx = bx + tx + 28;
                float v = 0.f;
                if (yy >= 0 && yy < IH && xx >= 0 && xx < IW) v = img[yy * IW + xx];
                sin_[r][tx + 32] = v;
            }
        }
    }
    __syncthreads();
    // ---- stage 1: gaussian, 4 outputs per thread (28 rows x 9 groups = 252) ----
    if (tid < 252) {
        const int r = tid / 9;
        const int c0 = (tid - r * 9) * 4;
        float W[5][8];
#pragma unroll
        for (int di = 0; di < 5; di++) {
            const float4 lo = *(const float4*)&sin_[r + di][c0];
            const float4 hi = *(const float4*)&sin_[r + di][c0 + 4];
            W[di][0] = lo.x; W[di][1] = lo.y; W[di][2] = lo.z; W[di][3] = lo.w;
            W[di][4] = hi.x; W[di][5] = hi.y; W[di][6] = hi.z; W[di][7] = hi.w;
        }
        float s0 = 0.f, s1 = 0.f, s2 = 0.f, s3 = 0.f;
#pragma unroll
        for (int di = 0; di < 5; di++)
#pragma unroll
            for (int dj = 0; dj < 5; dj++) {
                const float wgt = GW[di * 5 + dj];
                s0 = fmaf(wgt, W[di][dj + 0], s0);
                s1 = fmaf(wgt, W[di][dj + 1], s1);
                s2 = fmaf(wgt, W[di][dj + 2], s2);
                s3 = fmaf(wgt, W[di][dj + 3], s3);
            }
        float4 o;
        if (interior) {
            o.x = s0 * (1.0f / 255.0f);
            o.y = s1 * (1.0f / 255.0f);
            o.z = s2 * (1.0f / 255.0f);
            o.w = s3 * (1.0f / 255.0f);
        } else {
            const int yy = by + r - 2;
            const bool rowOk = (yy >= 0 && yy < IH);
            const int xx0 = bx + c0 - 2;
            o.x = (rowOk && xx0 + 0 >= 0 && xx0 + 0 < IW) ? s0 * (1.0f / 255.0f) : 0.f;
            o.y = (rowOk && xx0 + 1 >= 0 && xx0 + 1 < IW) ? s1 * (1.0f / 255.0f) : 0.f;
            o.z = (rowOk && xx0 + 2 >= 0 && xx0 + 2 < IW) ? s2 * (1.0f / 255.0f) : 0.f;
            o.w = (rowOk && xx0 + 3 >= 0 && xx0 + 3 < IW) ? s3 * (1.0f / 255.0f) : 0.f;
        }
        *(float4*)&gsm[r][c0] = o;
    }
    __syncthreads();
    // ---- stage 2a: interior 4-col groups (24 rows x 8 groups = 192 threads) ----
    // magS row r <-> image Y = by + r - 1; window rows = r, r+1, r+2.
    const bool colBorder = (blockIdx.x == 0) | (blockIdx.x == WPR - 1);
    if (tid < 192) {
        const int r = (tid >> 3) + 1;          // 1..24
        const int k = tid & 7;                 // 0..7
        float w0[8], w1[8], w2[8];
        {
            const float4 a0 = *(const float4*)&gsm[r][4 * k];
            const float4 a1 = *(const float4*)&gsm[r][4 * k + 4];
            w0[0]=a0.x; w0[1]=a0.y; w0[2]=a0.z; w0[3]=a0.w;
            w0[4]=a1.x; w0[5]=a1.y; w0[6]=a1.z; w0[7]=a1.w;
            const float4 b0 = *(const float4*)&gsm[r + 1][4 * k];
            const float4 b1 = *(const float4*)&gsm[r + 1][4 * k + 4];
            w1[0]=b0.x; w1[1]=b0.y; w1[2]=b0.z; w1[3]=b0.w;
            w1[4]=b1.x; w1[5]=b1.y; w1[6]=b1.z; w1[7]=b1.w;
            const float4 c0_ = *(const float4*)&gsm[r + 2][4 * k];
            const float4 c1_ = *(const float4*)&gsm[r + 2][4 * k + 4];
            w2[0]=c0_.x; w2[1]=c0_.y; w2[2]=c0_.z; w2[3]=c0_.w;
            w2[4]=c1_.x; w2[5]=c1_.y; w2[6]=c1_.z; w2[7]=c1_.w;
        }
        float mg[4], an[4];
        unsigned int clsPack = 0;
#pragma unroll
        for (int j = 0; j < 4; j++) {
            float gx_, gy_;
            sobel_win(w0[j+1], w0[j+2], w0[j+3],
                      w1[j+1],          w1[j+3],
                      w2[j+1], w2[j+2], w2[j+3], gx_, gy_);
            mg[j] = sqrtf(gx_ * gx_ + gy_ * gy_ + 1e-6f) * 255.0f;
            float am; int cls;
            ang_chain(gx_, gy_, am, cls);
            an[j] = am;
            clsPack |= (unsigned)cls << (8 * j);
        }
        *(float4*)&magS[r][4 * k + 4] = make_float4(mg[0], mg[1], mg[2], mg[3]);
        dirS[r - 1][k] = clsPack;
        const int Y = by + r - 1;
        const int idx = b * NPIX + Y * IW + bx + 4 * k;
        *(float4*)&magOut[idx] = make_float4(mg[0], mg[1], mg[2], mg[3]);
        *(float4*)&angOut[idx] = make_float4(an[0], an[1], an[2], an[3]);
        if (Y == 0 || Y == IH - 1 || colBorder) {
            uchar4 d4;
            d4.x = (unsigned char)(clsPack & 3);
            d4.y = (unsigned char)((clsPack >> 8) & 3);
            d4.z = (unsigned char)((clsPack >> 16) & 3);
            d4.w = (unsigned char)((clsPack >> 24) & 3);
            *(uchar4*)&g_dir[idx] = d4;
        }
    } else {
        // ---- stage 2b on warps 6-7 (64 threads, 116 halo-ring items) ----
#pragma unroll
        for (int it = 0; it < 2; it++) {
            const int u = (tid - 192) + it * 64;
            if (u < 116) {
                int r, c;
                if (u < 34)      { r = 0;         c = 3 + u; }
                else if (u < 68) { r = 25;        c = 3 + (u - 34); }
                else if (u < 92) { r = u - 67;    c = 3; }          // rows 1..24
                else             { r = u - 91;    c = 36; }         // rows 1..24
                float gxv, gyv;
                sobel_px(gsm, r, c - 3, gxv, gyv);  // window rows r..r+2, cols c-3..c-1
                magS[r][c] = sqrtf(gxv * gxv + gyv * gyv + 1e-6f) * 255.0f;
            }
        }
    }
    __syncthreads();
    // ---- stage 3: NMS only (3 rows per thread) ----
#pragma unroll
    for (int s = 0; s < 3; s++) {
        const int o = ty + 8 * s;            // output row within tile (warp-uniform)
        const int Y = by + o;
        const int r0 = o + 1, c0 = tx + 4;   // magS coords of own pixel
        const float m255 = magS[r0][c0];
        const int cls = (int)((dirS[o][tx >> 2] >> (8 * (tx & 3))) & 3u);
        // cls0: (y,xr)/(y,xl)  cls1: (yd,xr)/(yu,x) [ref bug kept]
        // cls2: (yd,x)/(yu,x)  cls3: (yd,xl)/(yu,xr)
        int ar = (cls == 0) ? r0 : r0 + 1;
        int ac = (cls == 2) ? c0 : ((cls == 3) ? c0 - 1 : c0 + 1);
        int cr = (cls == 0) ? r0 : r0 - 1;
        int cc = (cls == 0) ? c0 - 1 : ((cls == 3) ? c0 + 1 : c0);
        float a = magS[ar][ac];
        float c = magS[cr][cc];
        float sup = (m255 > a && m255 > c) ? m255 : 0.f;
        unsigned we = __ballot_sync(0xffffffffu, sup > 150.0f);
        unsigned wl = __ballot_sync(0xffffffffu, sup >= 50.0f && sup < 150.0f);
        if (tx == 0) {
            const int widx = (b * IH + Y) * WPR + blockIdx.x;
            g_pe0[widx] = we;
            g_pl0[widx] = wl;
        }
    }
}

// ---------------------------------------------------------------------------
// Kernel 2: recompute NMS/threshold for border words (rows 0 & 1079, word
// cols 0 & 59) with jnp.roll wrap-around. One warp per word.
// ---------------------------------------------------------------------------
__global__ void k_border(const float* __restrict__ mag) {
    const int W = blockIdx.x * 8 + threadIdx.y;          // warp id
    const int lane = threadIdx.x;
    const int b = W / BORDER_WORDS_PER_IMG;
    const int u = W % BORDER_WORDS_PER_IMG;
    int y, w;
    if (u < 60)       { y = 0;        w = u; }
    else if (u < 120) { y = IH - 1;   w = u - 60; }
    else { int v = u - 120; y = 1 + (v >> 1); w = (v & 1) ? (WPR - 1) : 0; }
    const int x = w * 32 + lane;
    const float* p = mag + b * NPIX;
    const int idx = b * NPIX + y * IW + x;
    const float m0 = p[y * IW + x];
    const int xl = (x == 0) ? (IW - 1) : (x - 1);
    const int xr = (x == IW - 1) ? 0 : (x + 1);
    const int yu = (y == 0) ? (IH - 1) : (y - 1);
    const int yd = (y == IH - 1) ? 0 : (y + 1);
    const int cls = g_dir[idx];
    int ay = (cls == 0) ? y : yd;
    int ax = (cls == 2) ? x : ((cls == 3) ? xl : xr);
    int cy = (cls == 0) ? y : yu;
    int cx = (cls == 0) ? xl : ((cls == 3) ? xr : x);
    float a = p[ay * IW + ax];
    float c = p[cy * IW + cx];
    float sup = (m0 > a && m0 > c) ? m0 : 0.f;
    unsigned we = __ballot_sync(0xffffffffu, sup > 150.0f);
    unsigned wl = __ballot_sync(0xffffffffu, sup >= 50.0f && sup < 150.0f);
    if (lane == 0) {
        const int widx = (b * IH + y) * WPR + w;
        g_pe0[widx] = we;
        g_pl0[widx] = wl;
    }
}

// ---------------------------------------------------------------------------
// Bit helper: OR of {left,center,right} horizontal neighbors of a word row.
// ---------------------------------------------------------------------------
__device__ __forceinline__ unsigned hor3(unsigned L, unsigned M, unsigned R) {
    return M | (M << 1) | (M >> 1) | (L >> 31) | (R << 31);
}

// ---------------------------------------------------------------------------
// Kernel 3: hysteresis iteration 1, fully bit-packed, word per thread.
// ---------------------------------------------------------------------------
__global__ void k_hyst1() {
    const int t = blockIdx.x * 256 + threadIdx.x;
    const int w = t % WPR;
    const int rem = t / WPR;
    const int y = rem % IH;
    const int base = t - w;
    unsigned nbr = 0, e = 0;
#pragma unroll
    for (int dy = -1; dy <= 1; dy++) {
        const int yy = y + dy;
        if (yy < 0 || yy >= IH) continue;
        const int rb = base + dy * WPR;
        unsigned L = (w > 0)       ? g_pe0[rb + w - 1] : 0u;
        unsigned M =                 g_pe0[rb + w];
        unsigned R = (w < WPR - 1) ? g_pe0[rb + w + 1] : 0u;
        nbr |= hor3(L, M, R);
        if (dy == 0) e = M;
    }
    const unsigned l = g_pl0[t];
    const unsigned conn = nbr & l;
    g_pe1[t] = e | conn;
    g_pl1[t] = l & ~conn;
}

// ---------------------------------------------------------------------------
// Kernel 4: hysteresis iteration 2 + final edges*255 float store.
// Word per thread; smem-staged, conflict-free, fully coalesced float output.
// ---------------------------------------------------------------------------
__global__ void k_hyst2(float* __restrict__ outE) {
    __shared__ float buf[256 * 33];
    const int t0 = blockIdx.x * 256;
    const int t = t0 + threadIdx.x;
    const int w = t % WPR;
    const int rem = t / WPR;
    const int y = rem % IH;
    const int base = t - w;
    unsigned nbr = 0, e = 0;
#pragma unroll
    for (int dy = -1; dy <= 1; dy++) {
        const int yy = y + dy;
        if (yy < 0 || yy >= IH) continue;
        const int rb = base + dy * WPR;
        unsigned L = (w > 0)       ? g_pe1[rb + w - 1] : 0u;
        unsigned M =                 g_pe1[rb + w];
        unsigned R = (w < WPR - 1) ? g_pe1[rb + w + 1] : 0u;
        nbr |= hor3(L, M, R);
        if (dy == 0) e = M;
    }
    const unsigned l = g_pl1[t];
    const unsigned enew = e | (nbr & l);
#pragma unroll
    for (int j = 0; j < 32; j++)
        buf[threadIdx.x * 33 + j] = ((enew >> j) & 1u) ? 255.0f : 0.0f;
    __syncthreads();
    const int gbase = t0 * 32;
#pragma unroll
    for (int i = 0; i < 32; i++) {
        const int k = i * 256 + threadIdx.x;
        outE[gbase + k] = buf[(k >> 5) * 33 + (k & 31)];
    }
}

extern "C" void kernel_launch(void* const* d_in, const int* in_sizes, int n_in,
                              void* d_out, int out_size) {
    const float* x = (const float*)d_in[0];
    float* out       = (float*)d_out;
    float* out_edges = out;
    float* out_mag   = out + NTOT;
    float* out_ang   = out + 2 * NTOT;

    dim3 blk(32, 8, 1);
    dim3 grd(IW / 32, IH / TH, IB);

    k_fused<<<grd, blk>>>(x, out_mag, out_ang);
    k_border<<<(IB * BORDER_WORDS_PER_IMG) / 8, blk>>>(out_mag);
    k_hyst1<<<NWORDS / 256, 256>>>();
    k_hyst2<<<NWORDS / 256, 256>>>(out_edges);
}

// round 13
// speedup vs baseline: 1.0881x; 1.0178x over previous
#include <cuda_runtime.h>

#define IW 1920
#define IH 1080
#define IB 8
#define NPIX (IW * IH)
#define NTOT (IB * NPIX)
#define WPR  (IW / 32)            // 60 packed words per row
#define NWORDS (NTOT / 32)        // 518400
#define BORDER_WORDS_PER_IMG (60 + 60 + 1078 * 2)   // 2276

#define TH 24                     // output tile height (1080/24 = 45)

// Scratch (no cudaMalloc allowed)
__device__ unsigned char g_dir[NTOT];
__device__ unsigned int  g_pe0[NWORDS], g_pl0[NWORDS];   // after NMS/threshold

// ang/deg/cls chain — bit-identical to previous rounds.
__device__ __forceinline__ void ang_chain(float gx_, float gy_, float& am, int& cls) {
    float ang = atan2f(gy_, gx_);
    float t = ang + 3.14159274101257324f;            // float32(pi)
    if (t >= 6.28318548202514648f) t -= 6.28318548202514648f;   // == fmodf(t, 2pi)
    float deg = t * 57.2957801818847656f;            // float32(180/pi)
    am = deg;
    if (am >= 180.0f) am -= 180.0f;                  // == fmodf(deg, 180)
    if (am >= 180.0f) am -= 180.0f;
    int q = (int)rintf(deg / 45.0f);                 // round-half-even == jnp.round
    cls = q & 3;
}

// Scalar sobel (halo ring). Window top-left (r,c): reads gsm[r..r+2][c..c+2].
__device__ __forceinline__ void sobel_px(const float (*gsm)[40], int r, int c,
                                         float& gxv, float& gyv) {
    const float v00 = gsm[r+0][c+0], v01 = gsm[r+0][c+1], v02 = gsm[r+0][c+2];
    const float v10 = gsm[r+1][c+0],                      v12 = gsm[r+1][c+2];
    const float v20 = gsm[r+2][c+0], v21 = gsm[r+2][c+1], v22 = gsm[r+2][c+2];
    float gx = 0.f;
    gx = fmaf(-0.125f, v00, gx);
    gx = fmaf( 0.125f, v02, gx);
    gx = fmaf(-0.25f,  v10, gx);
    gx = fmaf( 0.25f,  v12, gx);
    gx = fmaf(-0.125f, v20, gx);
    gx = fmaf( 0.125f, v22, gx);
    float gy = 0.f;
    gy = fmaf(-0.125f, v00, gy);
    gy = fmaf(-0.25f,  v01, gy);
    gy = fmaf(-0.125f, v02, gy);
    gy = fmaf( 0.125f, v20, gy);
    gy = fmaf( 0.25f,  v21, gy);
    gy = fmaf( 0.125f, v22, gy);
    gxv = gx; gyv = gy;
}

// ---------------------------------------------------------------------------
// Kernel 1: fused gaussian(5x5) + sobel + mag*255 + ang + NMS + threshold.
// Row-streaming stages (low register pressure); interior fast path; STG.128.
// Border words (jnp.roll wrap) recomputed by k_border afterwards.
// ---------------------------------------------------------------------------
__global__ void k_fused(const float* __restrict__ x,
                        float* __restrict__ magOut, float* __restrict__ angOut) {
    constexpr float GW[25] = {
        2.0f/159.0f, 4.0f/159.0f,  5.0f/159.0f, 4.0f/159.0f, 2.0f/159.0f,
        4.0f/159.0f, 9.0f/159.0f, 12.0f/159.0f, 9.0f/159.0f, 4.0f/159.0f,
        5.0f/159.0f,12.0f/159.0f, 15.0f/159.0f,12.0f/159.0f, 5.0f/159.0f,
        4.0f/159.0f, 9.0f/159.0f, 12.0f/159.0f, 9.0f/159.0f, 4.0f/159.0f,
        2.0f/159.0f, 4.0f/159.0f,  5.0f/159.0f, 4.0f/159.0f, 2.0f/159.0f };
    __shared__ float sin_[32][40];     // raw input, rows by-4..by+27, cols bx-4..bx+35
    __shared__ float gsm[28][40];      // smoothed/255, row r <-> Y=by+r-2, col c <-> X=bx+c-2 (36 used)
    __shared__ float magS[26][40];     // mag*255, row r <-> Y=by+r-1, col c <-> X=bx+c-4 (c 3..36 used)
    __shared__ unsigned int dirS[24][8]; // packed cls, 4 px per word
    const int b  = blockIdx.z;
    const int bx = blockIdx.x * 32, by = blockIdx.y * TH;
    const int tx = threadIdx.x, ty = threadIdx.y;
    const int tid = ty * 32 + tx;
    const float* img = x + b * NPIX;
    const bool interior = (blockIdx.x > 0) & (blockIdx.x < 59) &
                          (blockIdx.y > 0) & (blockIdx.y < 44);
    // ---- stage 0: raw input tile ----
    if (interior) {
#pragma unroll
        for (int it = 0; it < 2; it++) {
            const int i = tid + it * 256;
            if (i < 320) {
                const int r = i / 10, c4 = i - r * 10;
                const int yy = by + r - 4;
                *(float4*)&sin_[r][4 * c4] =
                    *(const float4*)&img[yy * IW + bx + 4 * c4 - 4];
            }
        }
    } else {
#pragma unroll
        for (int k = 0; k < 4; k++) {
            const int r = ty + 8 * k;
            const int yy = by + r - 4;
            {
                const int xx = bx + tx - 4;
                float v = 0.f;
                if (yy >= 0 && yy < IH && xx >= 0 && xx < IW) v = img[yy * IW + xx];
                sin_[r][tx] = v;
            }
            if (tx < 8) {
                const int xx = bx + tx + 28;
                float v = 0.f;
                if (yy >= 0 && yy < IH && xx >= 0 && xx < IW) v = img[yy * IW + xx];
                sin_[r][tx + 32] = v;
            }
        }
    }
    __syncthreads();
    // ---- stage 1: gaussian, 4 outputs per thread, row-streamed ----
    if (tid < 252) {
        const int r = tid / 9;
        const int c0 = (tid - r * 9) * 4;
        float s0 = 0.f, s1 = 0.f, s2 = 0.f, s3 = 0.f;
#pragma unroll
        for (int di = 0; di < 5; di++) {
            const float4 lo = *(const float4*)&sin_[r + di][c0];
            const float4 hi = *(const float4*)&sin_[r + di][c0 + 4];
            const float v[8] = {lo.x, lo.y, lo.z, lo.w, hi.x, hi.y, hi.z, hi.w};
#pragma unroll
            for (int dj = 0; dj < 5; dj++) {
                const float wgt = GW[di * 5 + dj];
                s0 = fmaf(wgt, v[dj + 0], s0);
                s1 = fmaf(wgt, v[dj + 1], s1);
                s2 = fmaf(wgt, v[dj + 2], s2);
                s3 = fmaf(wgt, v[dj + 3], s3);
            }
        }
        float4 o;
        if (interior) {
            o.x = s0 * (1.0f / 255.0f);
            o.y = s1 * (1.0f / 255.0f);
            o.z = s2 * (1.0f / 255.0f);
            o.w = s3 * (1.0f / 255.0f);
        } else {
            const int yy = by + r - 2;
            const bool rowOk = (yy >= 0 && yy < IH);
            const int xx0 = bx + c0 - 2;
            o.x = (rowOk && xx0 + 0 >= 0 && xx0 + 0 < IW) ? s0 * (1.0f / 255.0f) : 0.f;
            o.y = (rowOk && xx0 + 1 >= 0 && xx0 + 1 < IW) ? s1 * (1.0f / 255.0f) : 0.f;
            o.z = (rowOk && xx0 + 2 >= 0 && xx0 + 2 < IW) ? s2 * (1.0f / 255.0f) : 0.f;
            o.w = (rowOk && xx0 + 3 >= 0 && xx0 + 3 < IW) ? s3 * (1.0f / 255.0f) : 0.f;
        }
        *(float4*)&gsm[r][c0] = o;
    }
    __syncthreads();
    // ---- stage 2a: interior 4-col groups, row-streamed sobel ----
    // magS row r <-> image Y = by + r - 1; window rows = r, r+1, r+2.
    const bool colBorder = (blockIdx.x == 0) | (blockIdx.x == WPR - 1);
    if (tid < 192) {
        const int r = (tid >> 3) + 1;          // 1..24
        const int k = tid & 7;                 // 0..7
        float gxv[4] = {0.f, 0.f, 0.f, 0.f};
        float gyv[4] = {0.f, 0.f, 0.f, 0.f};
#pragma unroll
        for (int rr = 0; rr < 3; rr++) {
            const float4 lo = *(const float4*)&gsm[r + rr][4 * k];
            const float4 hi = *(const float4*)&gsm[r + rr][4 * k + 4];
            const float v[8] = {lo.x, lo.y, lo.z, lo.w, hi.x, hi.y, hi.z, hi.w};
#pragma unroll
            for (int j = 0; j < 4; j++) {
                const float a = v[j + 1], m = v[j + 2], c = v[j + 3];
                if (rr == 0) {
                    gxv[j] = fmaf(-0.125f, a, gxv[j]);
                    gxv[j] = fmaf( 0.125f, c, gxv[j]);
                    gyv[j] = fmaf(-0.125f, a, gyv[j]);
                    gyv[j] = fmaf(-0.25f,  m, gyv[j]);
                    gyv[j] = fmaf(-0.125f, c, gyv[j]);
                } else if (rr == 1) {
                    gxv[j] = fmaf(-0.25f,  a, gxv[j]);
                    gxv[j] = fmaf( 0.25f,  c, gxv[j]);
                } else {
                    gxv[j] = fmaf(-0.125f, a, gxv[j]);
                    gxv[j] = fmaf( 0.125f, c, gxv[j]);
                    gyv[j] = fmaf( 0.125f, a, gyv[j]);
                    gyv[j] = fmaf( 0.25f,  m, gyv[j]);
                    gyv[j] = fmaf( 0.125f, c, gyv[j]);
                }
            }
        }
        float mg[4], an[4];
        unsigned int clsPack = 0;
#pragma unroll
        for (int j = 0; j < 4; j++) {
            mg[j] = sqrtf(gxv[j] * gxv[j] + gyv[j] * gyv[j] + 1e-6f) * 255.0f;
            float am; int cls;
            ang_chain(gxv[j], gyv[j], am, cls);
            an[j] = am;
            clsPack |= (unsigned)cls << (8 * j);
        }
        *(float4*)&magS[r][4 * k + 4] = make_float4(mg[0], mg[1], mg[2], mg[3]);
        dirS[r - 1][k] = clsPack;
        const int Y = by + r - 1;
        const int idx = b * NPIX + Y * IW + bx + 4 * k;
        *(float4*)&magOut[idx] = make_float4(mg[0], mg[1], mg[2], mg[3]);
        *(float4*)&angOut[idx] = make_float4(an[0], an[1], an[2], an[3]);
        if (Y == 0 || Y == IH - 1 || colBorder) {
            uchar4 d4;
            d4.x = (unsigned char)(clsPack & 3);
            d4.y = (unsigned char)((clsPack >> 8) & 3);
            d4.z = (unsigned char)((clsPack >> 16) & 3);
            d4.w = (unsigned char)((clsPack >> 24) & 3);
            *(uchar4*)&g_dir[idx] = d4;
        }
    } else {
        // ---- stage 2b on warps 6-7 (64 threads, 116 halo-ring items) ----
#pragma unroll
        for (int it = 0; it < 2; it++) {
            const int u = (tid - 192) + it * 64;
            if (u < 116) {
                int r, c;
                if (u < 34)      { r = 0;         c = 3 + u; }
                else if (u < 68) { r = 25;        c = 3 + (u - 34); }
                else if (u < 92) { r = u - 67;    c = 3; }          // rows 1..24
                else             { r = u - 91;    c = 36; }         // rows 1..24
                float gxv, gyv;
                sobel_px(gsm, r, c - 3, gxv, gyv);  // window rows r..r+2, cols c-3..c-1
                magS[r][c] = sqrtf(gxv * gxv + gyv * gyv + 1e-6f) * 255.0f;
            }
        }
    }
    __syncthreads();
    // ---- stage 3: NMS only (3 rows per thread) ----
#pragma unroll
    for (int s = 0; s < 3; s++) {
        const int o = ty + 8 * s;            // output row within tile (warp-uniform)
        const int Y = by + o;
        const int r0 = o + 1, c0 = tx + 4;   // magS coords of own pixel
        const float m255 = magS[r0][c0];
        const int cls = (int)((dirS[o][tx >> 2] >> (8 * (tx & 3))) & 3u);
        // cls0: (y,xr)/(y,xl)  cls1: (yd,xr)/(yu,x) [ref bug kept]
        // cls2: (yd,x)/(yu,x)  cls3: (yd,xl)/(yu,xr)
        int ar = (cls == 0) ? r0 : r0 + 1;
        int ac = (cls == 2) ? c0 : ((cls == 3) ? c0 - 1 : c0 + 1);
        int cr = (cls == 0) ? r0 : r0 - 1;
        int cc = (cls == 0) ? c0 - 1 : ((cls == 3) ? c0 + 1 : c0);
        float a = magS[ar][ac];
        float c = magS[cr][cc];
        float sup = (m255 > a && m255 > c) ? m255 : 0.f;
        unsigned we = __ballot_sync(0xffffffffu, sup > 150.0f);
        unsigned wl = __ballot_sync(0xffffffffu, sup >= 50.0f && sup < 150.0f);
        if (tx == 0) {
            const int widx = (b * IH + Y) * WPR + blockIdx.x;
            g_pe0[widx] = we;
            g_pl0[widx] = wl;
        }
    }
}

// ---------------------------------------------------------------------------
// Kernel 2: recompute NMS/threshold for border words (rows 0 & 1079, word
// cols 0 & 59) with jnp.roll wrap-around. One warp per word.
// ---------------------------------------------------------------------------
__global__ void k_border(const float* __restrict__ mag) {
    const int W = blockIdx.x * 8 + threadIdx.y;          // warp id
    const int lane = threadIdx.x;
    const int b = W / BORDER_WORDS_PER_IMG;
    const int u = W % BORDER_WORDS_PER_IMG;
    int y, w;
    if (u < 60)       { y = 0;        w = u; }
    else if (u < 120) { y = IH - 1;   w = u - 60; }
    else { int v = u - 120; y = 1 + (v >> 1); w = (v & 1) ? (WPR - 1) : 0; }
    const int x = w * 32 + lane;
    const float* p = mag + b * NPIX;
    const int idx = b * NPIX + y * IW + x;
    const float m0 = p[y * IW + x];
    const int xl = (x == 0) ? (IW - 1) : (x - 1);
    const int xr = (x == IW - 1) ? 0 : (x + 1);
    const int yu = (y == 0) ? (IH - 1) : (y - 1);
    const int yd = (y == IH - 1) ? 0 : (y + 1);
    const int cls = g_dir[idx];
    int ay = (cls == 0) ? y : yd;
    int ax = (cls == 2) ? x : ((cls == 3) ? xl : xr);
    int cy = (cls == 0) ? y : yu;
    int cx = (cls == 0) ? xl : ((cls == 3) ? xr : x);
    float a = p[ay * IW + ax];
    float c = p[cy * IW + cx];
    float sup = (m0 > a && m0 > c) ? m0 : 0.f;
    unsigned we = __ballot_sync(0xffffffffu, sup > 150.0f);
    unsigned wl = __ballot_sync(0xffffffffu, sup >= 50.0f && sup < 150.0f);
    if (lane == 0) {
        const int widx = (b * IH + y) * WPR + w;
        g_pe0[widx] = we;
        g_pl0[widx] = wl;
    }
}

// ---------------------------------------------------------------------------
// Bit helper: OR of {left,center,right} horizontal neighbors of a word row.
// ---------------------------------------------------------------------------
__device__ __forceinline__ unsigned hor3(unsigned L, unsigned M, unsigned R) {
    return M | (M << 1) | (M >> 1) | (L >> 31) | (R << 31);
}

// ---------------------------------------------------------------------------
// Kernel 3: BOTH hysteresis iterations fused + final edges*255 float store.
// iter2 needs iter1 at rows y-1..y+1; the neighbor words' iter1 contribution
// enters only via bit31 (left) / bit0 (right), which depend only on words
// w-1..w+1 of pe0 (hor3's bit31 = M.b31|M.b30|R.b0; bit0 = M.b0|M.b1|L.b31).
// ---------------------------------------------------------------------------
__global__ void k_hyst(float* __restrict__ outE) {
    __shared__ float buf[256 * 33];
    const int t0 = blockIdx.x * 256;
    const int t = t0 + threadIdx.x;
    const int w = t % WPR;
    const int rem = t / WPR;
    const int y = rem % IH;
    const int base = t - w;                 // word index of (b, y, 0)
    // load pe0 rows y-2..y+2 x words w-1..w+1 ; pl0 rows y-1..y+1 x w-1..w+1
    unsigned pe[5][3], pl[3][3];
#pragma unroll
    for (int dy = -2; dy <= 2; dy++) {
        const int yy = y + dy;
#pragma unroll
        for (int dw = -1; dw <= 1; dw++) {
            const int ww = w + dw;
            unsigned v = 0u;
            if (yy >= 0 && yy < IH && ww >= 0 && ww < WPR)
                v = g_pe0[base + dy * WPR + dw];
            pe[dy + 2][dw + 1] = v;
        }
    }
#pragma unroll
    for (int dy = -1; dy <= 1; dy++) {
        const int yy = y + dy;
#pragma unroll
        for (int dw = -1; dw <= 1; dw++) {
            const int ww = w + dw;
            unsigned v = 0u;
            if (yy >= 0 && yy < IH && ww >= 0 && ww < WPR)
                v = g_pl0[base + dy * WPR + dw];
            pl[dy + 1][dw + 1] = v;
        }
    }
    // iter1: center words for rows y-1..y+1 (+ boundary bits of side words)
    unsigned e1c[3], eL31[3], eR0[3];
    unsigned nbr_center = 0;
#pragma unroll
    for (int i = 0; i < 3; i++) {           // row yy = y-1+i ; pe row idx i+1
        unsigned nbr = 0, nbrL = 0, nbrR = 0;
#pragma unroll
        for (int rr = i; rr <= i + 2; rr++) {
            nbr  |= hor3(pe[rr][0], pe[rr][1], pe[rr][2]);
            nbrL |= pe[rr][0] | (pe[rr][0] << 1) | (pe[rr][1] << 31);
            nbrR |= pe[rr][2] | (pe[rr][2] >> 1) | (pe[rr][1] >> 31);
        }
        e1c[i]  = pe[i + 1][1] | (nbr & pl[i][1]);
        eL31[i] = (pe[i + 1][0] | (nbrL & pl[i][0])) & 0x80000000u;
        eR0[i]  = (pe[i + 1][2] | (nbrR & pl[i][2])) & 1u;
        if (i == 1) nbr_center = nbr;
    }
    const unsigned l1 = pl[1][1] & ~nbr_center;
    // iter2
    unsigned nbr2 = 0;
#pragma unroll
    for (int i = 0; i < 3; i++)
        nbr2 |= e1c[i] | (e1c[i] << 1) | (e1c[i] >> 1) |
                (eL31[i] >> 31) | (eR0[i] << 31);
    const unsigned enew = e1c[1] | (nbr2 & l1);
    // expand + coalesced store
#pragma unroll
    for (int j = 0; j < 32; j++)
        buf[threadIdx.x * 33 + j] = ((enew >> j) & 1u) ? 255.0f : 0.0f;
    __syncthreads();
    const int gbase = t0 * 32;
#pragma unroll
    for (int i = 0; i < 32; i++) {
        const int k = i * 256 + threadIdx.x;
        outE[gbase + k] = buf[(k >> 5) * 33 + (k & 31)];
    }
}

extern "C" void kernel_launch(void* const* d_in, const int* in_sizes, int n_in,
                              void* d_out, int out_size) {
    const float* x = (const float*)d_in[0];
    float* out       = (float*)d_out;
    float* out_edges = out;
    float* out_mag   = out + NTOT;
    float* out_ang   = out + 2 * NTOT;

    dim3 blk(32, 8, 1);
    dim3 grd(IW / 32, IH / TH, IB);

    k_fused<<<grd, blk>>>(x, out_mag, out_ang);
    k_border<<<(IB * BORDER_WORDS_PER_IMG) / 8, blk>>>(out_mag);
    k_hyst<<<NWORDS / 256, 256>>>(out_edges);
}

// round 14
// speedup vs baseline: 1.1206x; 1.0299x over previous
#include <cuda_runtime.h>

#define IW 1920
#define IH 1080
#define IB 8
#define NPIX (IW * IH)
#define NTOT (IB * NPIX)
#define WPR  (IW / 32)            // 60 packed words per row
#define NWORDS (NTOT / 32)        // 518400
#define BORDER_WORDS_PER_IMG (60 + 60 + 1078 * 2)   // 2276

#define TH 24                     // output tile height (1080/24 = 45)

// Scratch (no cudaMalloc allowed)
__device__ unsigned char g_dir[NTOT];
__device__ unsigned int  g_pe0[NWORDS], g_pl0[NWORDS];   // after NMS/threshold

// ang/deg/cls chain — bit-identical to previous rounds.
__device__ __forceinline__ void ang_chain(float gx_, float gy_, float& am, int& cls) {
    float ang = atan2f(gy_, gx_);
    float t = ang + 3.14159274101257324f;            // float32(pi)
    if (t >= 6.28318548202514648f) t -= 6.28318548202514648f;   // == fmodf(t, 2pi)
    float deg = t * 57.2957801818847656f;            // float32(180/pi)
    am = deg;
    if (am >= 180.0f) am -= 180.0f;                  // == fmodf(deg, 180)
    if (am >= 180.0f) am -= 180.0f;
    int q = (int)rintf(deg / 45.0f);                 // round-half-even == jnp.round
    cls = q & 3;
}

// Scalar sobel (halo ring). Window top-left (r,c): reads gsm[r..r+2][c..c+2].
__device__ __forceinline__ void sobel_px(const float (*gsm)[40], int r, int c,
                                         float& gxv, float& gyv) {
    const float v00 = gsm[r+0][c+0], v01 = gsm[r+0][c+1], v02 = gsm[r+0][c+2];
    const float v10 = gsm[r+1][c+0],                      v12 = gsm[r+1][c+2];
    const float v20 = gsm[r+2][c+0], v21 = gsm[r+2][c+1], v22 = gsm[r+2][c+2];
    float gx = 0.f;
    gx = fmaf(-0.125f, v00, gx);
    gx = fmaf( 0.125f, v02, gx);
    gx = fmaf(-0.25f,  v10, gx);
    gx = fmaf( 0.25f,  v12, gx);
    gx = fmaf(-0.125f, v20, gx);
    gx = fmaf( 0.125f, v22, gx);
    float gy = 0.f;
    gy = fmaf(-0.125f, v00, gy);
    gy = fmaf(-0.25f,  v01, gy);
    gy = fmaf(-0.125f, v02, gy);
    gy = fmaf( 0.125f, v20, gy);
    gy = fmaf( 0.25f,  v21, gy);
    gy = fmaf( 0.125f, v22, gy);
    gxv = gx; gyv = gy;
}

// ---------------------------------------------------------------------------
// Kernel 1: fused gaussian(5x5) + sobel + mag*255 + ang + NMS + threshold.
// Row-streamed stages; NMS fused into the stage-2a thread mapping (m255/cls
// stay in registers; ballot words assembled with SHFL.BFLY ORs).
// Border words (jnp.roll wrap) recomputed by k_border afterwards.
// ---------------------------------------------------------------------------
__global__ void k_fused(const float* __restrict__ x,
                        float* __restrict__ magOut, float* __restrict__ angOut) {
    constexpr float GW[25] = {
        2.0f/159.0f, 4.0f/159.0f,  5.0f/159.0f, 4.0f/159.0f, 2.0f/159.0f,
        4.0f/159.0f, 9.0f/159.0f, 12.0f/159.0f, 9.0f/159.0f, 4.0f/159.0f,
        5.0f/159.0f,12.0f/159.0f, 15.0f/159.0f,12.0f/159.0f, 5.0f/159.0f,
        4.0f/159.0f, 9.0f/159.0f, 12.0f/159.0f, 9.0f/159.0f, 4.0f/159.0f,
        2.0f/159.0f, 4.0f/159.0f,  5.0f/159.0f, 4.0f/159.0f, 2.0f/159.0f };
    __shared__ float sin_[32][40];     // raw input, rows by-4..by+27, cols bx-4..bx+35
    __shared__ float gsm[28][40];      // smoothed/255, row r <-> Y=by+r-2, col c <-> X=bx+c-2 (36 used)
    __shared__ float magS[26][40];     // mag*255, row r <-> Y=by+r-1, col c <-> X=bx+c-4 (c 3..36 used)
    const int b  = blockIdx.z;
    const int bx = blockIdx.x * 32, by = blockIdx.y * TH;
    const int tx = threadIdx.x, ty = threadIdx.y;
    const int tid = ty * 32 + tx;
    const float* img = x + b * NPIX;
    const bool interior = (blockIdx.x > 0) & (blockIdx.x < 59) &
                          (blockIdx.y > 0) & (blockIdx.y < 44);
    // ---- stage 0: raw input tile ----
    if (interior) {
#pragma unroll
        for (int it = 0; it < 2; it++) {
            const int i = tid + it * 256;
            if (i < 320) {
                const int r = i / 10, c4 = i - r * 10;
                const int yy = by + r - 4;
                *(float4*)&sin_[r][4 * c4] =
                    *(const float4*)&img[yy * IW + bx + 4 * c4 - 4];
            }
        }
    } else {
#pragma unroll
        for (int k = 0; k < 4; k++) {
            const int r = ty + 8 * k;
            const int yy = by + r - 4;
            {
                const int xx = bx + tx - 4;
                float v = 0.f;
                if (yy >= 0 && yy < IH && xx >= 0 && xx < IW) v = img[yy * IW + xx];
                sin_[r][tx] = v;
            }
            if (tx < 8) {
                const int xx = bx + tx + 28;
                float v = 0.f;
                if (yy >= 0 && yy < IH && xx >= 0 && xx < IW) v = img[yy * IW + xx];
                sin_[r][tx + 32] = v;
            }
        }
    }
    __syncthreads();
    // ---- stage 1: gaussian, 4 outputs per thread, row-streamed ----
    if (tid < 252) {
        const int r = tid / 9;
        const int c0 = (tid - r * 9) * 4;
        float s0 = 0.f, s1 = 0.f, s2 = 0.f, s3 = 0.f;
#pragma unroll
        for (int di = 0; di < 5; di++) {
            const float4 lo = *(const float4*)&sin_[r + di][c0];
            const float4 hi = *(const float4*)&sin_[r + di][c0 + 4];
            const float v[8] = {lo.x, lo.y, lo.z, lo.w, hi.x, hi.y, hi.z, hi.w};
#pragma unroll
            for (int dj = 0; dj < 5; dj++) {
                const float wgt = GW[di * 5 + dj];
                s0 = fmaf(wgt, v[dj + 0], s0);
                s1 = fmaf(wgt, v[dj + 1], s1);
                s2 = fmaf(wgt, v[dj + 2], s2);
                s3 = fmaf(wgt, v[dj + 3], s3);
            }
        }
        float4 o;
        if (interior) {
            o.x = s0 * (1.0f / 255.0f);
            o.y = s1 * (1.0f / 255.0f);
            o.z = s2 * (1.0f / 255.0f);
            o.w = s3 * (1.0f / 255.0f);
        } else {
            const int yy = by + r - 2;
            const bool rowOk = (yy >= 0 && yy < IH);
            const int xx0 = bx + c0 - 2;
            o.x = (rowOk && xx0 + 0 >= 0 && xx0 + 0 < IW) ? s0 * (1.0f / 255.0f) : 0.f;
            o.y = (rowOk && xx0 + 1 >= 0 && xx0 + 1 < IW) ? s1 * (1.0f / 255.0f) : 0.f;
            o.z = (rowOk && xx0 + 2 >= 0 && xx0 + 2 < IW) ? s2 * (1.0f / 255.0f) : 0.f;
            o.w = (rowOk && xx0 + 3 >= 0 && xx0 + 3 < IW) ? s3 * (1.0f / 255.0f) : 0.f;
        }
        *(float4*)&gsm[r][c0] = o;
    }
    __syncthreads();
    // ---- stage 2a: interior 4-col groups, row-streamed sobel ----
    // magS row r <-> image Y = by + r - 1; window rows = r, r+1, r+2.
    const bool colBorder = (blockIdx.x == 0) | (blockIdx.x == WPR - 1);
    const int r = (tid >> 3) + 1;          // 1..24 (tid<192)
    const int k = tid & 7;                 // 0..7
    float mg[4];
    unsigned int clsPack = 0;
    if (tid < 192) {
        float gxv[4] = {0.f, 0.f, 0.f, 0.f};
        float gyv[4] = {0.f, 0.f, 0.f, 0.f};
#pragma unroll
        for (int rr = 0; rr < 3; rr++) {
            const float4 lo = *(const float4*)&gsm[r + rr][4 * k];
            const float4 hi = *(const float4*)&gsm[r + rr][4 * k + 4];
            const float v[8] = {lo.x, lo.y, lo.z, lo.w, hi.x, hi.y, hi.z, hi.w};
#pragma unroll
            for (int j = 0; j < 4; j++) {
                const float a = v[j + 1], m = v[j + 2], c = v[j + 3];
                if (rr == 0) {
                    gxv[j] = fmaf(-0.125f, a, gxv[j]);
                    gxv[j] = fmaf( 0.125f, c, gxv[j]);
                    gyv[j] = fmaf(-0.125f, a, gyv[j]);
                    gyv[j] = fmaf(-0.25f,  m, gyv[j]);
                    gyv[j] = fmaf(-0.125f, c, gyv[j]);
                } else if (rr == 1) {
                    gxv[j] = fmaf(-0.25f,  a, gxv[j]);
                    gxv[j] = fmaf( 0.25f,  c, gxv[j]);
                } else {
                    gxv[j] = fmaf(-0.125f, a, gxv[j]);
                    gxv[j] = fmaf( 0.125f, c, gxv[j]);
                    gyv[j] = fmaf( 0.125f, a, gyv[j]);
                    gyv[j] = fmaf( 0.25f,  m, gyv[j]);
                    gyv[j] = fmaf( 0.125f, c, gyv[j]);
                }
            }
        }
        float an[4];
#pragma unroll
        for (int j = 0; j < 4; j++) {
            mg[j] = sqrtf(gxv[j] * gxv[j] + gyv[j] * gyv[j] + 1e-6f) * 255.0f;
            float am; int cls;
            ang_chain(gxv[j], gyv[j], am, cls);
            an[j] = am;
            clsPack |= (unsigned)cls << (8 * j);
        }
        *(float4*)&magS[r][4 * k + 4] = make_float4(mg[0], mg[1], mg[2], mg[3]);
        const int Y = by + r - 1;
        const int idx = b * NPIX + Y * IW + bx + 4 * k;
        *(float4*)&magOut[idx] = make_float4(mg[0], mg[1], mg[2], mg[3]);
        *(float4*)&angOut[idx] = make_float4(an[0], an[1], an[2], an[3]);
        if (Y == 0 || Y == IH - 1 || colBorder) {
            uchar4 d4;
            d4.x = (unsigned char)(clsPack & 3);
            d4.y = (unsigned char)((clsPack >> 8) & 3);
            d4.z = (unsigned char)((clsPack >> 16) & 3);
            d4.w = (unsigned char)((clsPack >> 24) & 3);
            *(uchar4*)&g_dir[idx] = d4;
        }
    } else {
        // ---- stage 2b on warps 6-7 (64 threads, 116 halo-ring items) ----
#pragma unroll
        for (int it = 0; it < 2; it++) {
            const int u = (tid - 192) + it * 64;
            if (u < 116) {
                int rr, cc;
                if (u < 34)      { rr = 0;         cc = 3 + u; }
                else if (u < 68) { rr = 25;        cc = 3 + (u - 34); }
                else if (u < 92) { rr = u - 67;    cc = 3; }          // rows 1..24
                else             { rr = u - 91;    cc = 36; }         // rows 1..24
                float gxv, gyv;
                sobel_px(gsm, rr, cc - 3, gxv, gyv);  // window rows rr..rr+2
                magS[rr][cc] = sqrtf(gxv * gxv + gyv * gyv + 1e-6f) * 255.0f;
            }
        }
    }
    __syncthreads();
    // ---- stage 3: NMS on the stage-2a mapping (m255/cls in registers) ----
    if (tid < 192) {
        unsigned ne = 0, nl = 0;
#pragma unroll
        for (int j = 0; j < 4; j++) {
            const int c0 = 4 * k + 4 + j;           // magS col of own pixel
            const int cls = (int)((clsPack >> (8 * j)) & 3u);
            const float m255 = mg[j];
            // cls0: (y,xr)/(y,xl)  cls1: (yd,xr)/(yu,x) [ref bug kept]
            // cls2: (yd,x)/(yu,x)  cls3: (yd,xl)/(yu,xr)
            int ar = (cls == 0) ? r : r + 1;
            int ac = (cls == 2) ? c0 : ((cls == 3) ? c0 - 1 : c0 + 1);
            int cr = (cls == 0) ? r : r - 1;
            int cc = (cls == 0) ? c0 - 1 : ((cls == 3) ? c0 + 1 : c0);
            float a = magS[ar][ac];
            float c = magS[cr][cc];
            float sup = (m255 > a && m255 > c) ? m255 : 0.f;
            ne |= (sup > 150.0f ? 1u : 0u) << j;
            nl |= ((sup >= 50.0f && sup < 150.0f) ? 1u : 0u) << j;
        }
        ne <<= 4 * k;
        nl <<= 4 * k;
#pragma unroll
        for (int m = 1; m < 8; m <<= 1) {
            ne |= __shfl_xor_sync(0xffffffffu, ne, m);
            nl |= __shfl_xor_sync(0xffffffffu, nl, m);
        }
        if (k == 0) {
            const int Y = by + r - 1;
            const int widx = (b * IH + Y) * WPR + blockIdx.x;
            g_pe0[widx] = ne;
            g_pl0[widx] = nl;
        }
    }
}

// ---------------------------------------------------------------------------
// Kernel 2: recompute NMS/threshold for border words (rows 0 & 1079, word
// cols 0 & 59) with jnp.roll wrap-around. One warp per word.
// ---------------------------------------------------------------------------
__global__ void k_border(const float* __restrict__ mag) {
    const int W = blockIdx.x * 8 + threadIdx.y;          // warp id
    const int lane = threadIdx.x;
    const int b = W / BORDER_WORDS_PER_IMG;
    const int u = W % BORDER_WORDS_PER_IMG;
    int y, w;
    if (u < 60)       { y = 0;        w = u; }
    else if (u < 120) { y = IH - 1;   w = u - 60; }
    else { int v = u - 120; y = 1 + (v >> 1); w = (v & 1) ? (WPR - 1) : 0; }
    const int x = w * 32 + lane;
    const float* p = mag + b * NPIX;
    const int idx = b * NPIX + y * IW + x;
    const float m0 = p[y * IW + x];
    const int xl = (x == 0) ? (IW - 1) : (x - 1);
    const int xr = (x == IW - 1) ? 0 : (x + 1);
    const int yu = (y == 0) ? (IH - 1) : (y - 1);
    const int yd = (y == IH - 1) ? 0 : (y + 1);
    const int cls = g_dir[idx];
    int ay = (cls == 0) ? y : yd;
    int ax = (cls == 2) ? x : ((cls == 3) ? xl : xr);
    int cy = (cls == 0) ? y : yu;
    int cx = (cls == 0) ? xl : ((cls == 3) ? xr : x);
    float a = p[ay * IW + ax];
    float c = p[cy * IW + cx];
    float sup = (m0 > a && m0 > c) ? m0 : 0.f;
    unsigned we = __ballot_sync(0xffffffffu, sup > 150.0f);
    unsigned wl = __ballot_sync(0xffffffffu, sup >= 50.0f && sup < 150.0f);
    if (lane == 0) {
        const int widx = (b * IH + y) * WPR + w;
        g_pe0[widx] = we;
        g_pl0[widx] = wl;
    }
}

// ---------------------------------------------------------------------------
// Bit helper: OR of {left,center,right} horizontal neighbors of a word row.
// ---------------------------------------------------------------------------
__device__ __forceinline__ unsigned hor3(unsigned L, unsigned M, unsigned R) {
    return M | (M << 1) | (M >> 1) | (L >> 31) | (R << 31);
}

// ---------------------------------------------------------------------------
// Kernel 3: BOTH hysteresis iterations fused + final edges*255 float store.
// ---------------------------------------------------------------------------
__global__ void k_hyst(float* __restrict__ outE) {
    __shared__ float buf[256 * 33];
    const int t0 = blockIdx.x * 256;
    const int t = t0 + threadIdx.x;
    const int w = t % WPR;
    const int rem = t / WPR;
    const int y = rem % IH;
    const int base = t - w;                 // word index of (b, y, 0)
    unsigned pe[5][3], pl[3][3];
#pragma unroll
    for (int dy = -2; dy <= 2; dy++) {
        const int yy = y + dy;
#pragma unroll
        for (int dw = -1; dw <= 1; dw++) {
            const int ww = w + dw;
            unsigned v = 0u;
            if (yy >= 0 && yy < IH && ww >= 0 && ww < WPR)
                v = g_pe0[base + dy * WPR + dw];
            pe[dy + 2][dw + 1] = v;
        }
    }
#pragma unroll
    for (int dy = -1; dy <= 1; dy++) {
        const int yy = y + dy;
#pragma unroll
        for (int dw = -1; dw <= 1; dw++) {
            const int ww = w + dw;
            unsigned v = 0u;
            if (yy >= 0 && yy < IH && ww >= 0 && ww < WPR)
                v = g_pl0[base + dy * WPR + dw];
            pl[dy + 1][dw + 1] = v;
        }
    }
    unsigned e1c[3], eL31[3], eR0[3];
    unsigned nbr_center = 0;
#pragma unroll
    for (int i = 0; i < 3; i++) {           // row yy = y-1+i ; pe row idx i+1
        unsigned nbr = 0, nbrL = 0, nbrR = 0;
#pragma unroll
        for (int rr = i; rr <= i + 2; rr++) {
            nbr  |= hor3(pe[rr][0], pe[rr][1], pe[rr][2]);
            nbrL |= pe[rr][0] | (pe[rr][0] << 1) | (pe[rr][1] << 31);
            nbrR |= pe[rr][2] | (pe[rr][2] >> 1) | (pe[rr][1] >> 31);
        }
        e1c[i]  = pe[i + 1][1] | (nbr & pl[i][1]);
        eL31[i] = (pe[i + 1][0] | (nbrL & pl[i][0])) & 0x80000000u;
        eR0[i]  = (pe[i + 1][2] | (nbrR & pl[i][2])) & 1u;
        if (i == 1) nbr_center = nbr;
    }
    const unsigned l1 = pl[1][1] & ~nbr_center;
    unsigned nbr2 = 0;
#pragma unroll
    for (int i = 0; i < 3; i++)
        nbr2 |= e1c[i] | (e1c[i] << 1) | (e1c[i] >> 1) |
                (eL31[i] >> 31) | (eR0[i] << 31);
    const unsigned enew = e1c[1] | (nbr2 & l1);
#pragma unroll
    for (int j = 0; j < 32; j++)
        buf[threadIdx.x * 33 + j] = ((enew >> j) & 1u) ? 255.0f : 0.0f;
    __syncthreads();
    const int gbase = t0 * 32;
#pragma unroll
    for (int i = 0; i < 32; i++) {
        const int kk = i * 256 + threadIdx.x;
        outE[gbase + kk] = buf[(kk >> 5) * 33 + (kk & 31)];
    }
}

extern "C" void kernel_launch(void* const* d_in, const int* in_sizes, int n_in,
                              void* d_out, int out_size) {
    const float* x = (const float*)d_in[0];
    float* out       = (float*)d_out;
    float* out_edges = out;
    float* out_mag   = out + NTOT;
    float* out_ang   = out + 2 * NTOT;

    dim3 blk(32, 8, 1);
    dim3 grd(IW / 32, IH / TH, IB);

    k_fused<<<grd, blk>>>(x, out_mag, out_ang);
    k_border<<<(IB * BORDER_WORDS_PER_IMG) / 8, blk>>>(out_mag);
    k_hyst<<<NWORDS / 256, 256>>>(out_edges);
}